// round 6
// baseline (speedup 1.0000x reference)
#include <cuda_runtime.h>
#include <cuda_bf16.h>
#include <cstdint>

#define NK 256
#define ND 64
#define NTHREADS 128
#define GRIDSZ 296
#define THRESH 2e-3f

// smem layout (all tile bases 1024-aligned for SW128 swizzle)
#define OFF_CSQ 0                       // 256 f32
#define OFF_CHI 1024                    // 256 x 128B bf16 (hi of -2c)
#define OFF_CLO (OFF_CHI + 32768)
#define OFF_XHI (OFF_CLO + 32768)       // 128 x 128B
#define OFF_XLO (OFF_XHI + 16384)
#define SMEM_TOTAL (OFF_XLO + 16384)    // 99328 B

__device__ __forceinline__ uint32_t smem_u32(const void* p) {
    uint32_t a;
    asm("{ .reg .u64 t; cvta.to.shared.u64 t, %1; cvt.u32.u64 %0, t; }" : "=r"(a) : "l"(p));
    return a;
}
__device__ __forceinline__ void ldsm_x4(uint32_t a[4], uint32_t addr) {
    asm volatile("ldmatrix.sync.aligned.m8n8.x4.shared.b16 {%0,%1,%2,%3}, [%4];"
        : "=r"(a[0]), "=r"(a[1]), "=r"(a[2]), "=r"(a[3]) : "r"(addr));
}
__device__ __forceinline__ void ldsm_x2(uint32_t b[2], uint32_t addr) {
    asm volatile("ldmatrix.sync.aligned.m8n8.x2.shared.b16 {%0,%1}, [%2];"
        : "=r"(b[0]), "=r"(b[1]) : "r"(addr));
}
__device__ __forceinline__ void mma16816(float c[4], const uint32_t a[4], const uint32_t b[2]) {
    asm volatile("mma.sync.aligned.m16n8k16.row.col.f32.bf16.bf16.f32 "
        "{%0,%1,%2,%3}, {%4,%5,%6,%7}, {%8,%9}, {%0,%1,%2,%3};"
        : "+f"(c[0]), "+f"(c[1]), "+f"(c[2]), "+f"(c[3])
        : "r"(a[0]), "r"(a[1]), "r"(a[2]), "r"(a[3]), "r"(b[0]), "r"(b[1]));
}
__device__ __forceinline__ bool ltk(float d, int k, float d2, int k2) {
    return d < d2 || (d == d2 && k < k2);
}
// top-3 insert, strict < (scan order is ascending k -> lower k wins ties)
__device__ __forceinline__ void upd3(float d, int k, float& b1, float& b2, float& b3,
                                     int& k1, int& k2, int& k3) {
    if (d < b1)      { b3 = b2; k3 = k2; b2 = b1; k2 = k1; b1 = d; k1 = k; }
    else if (d < b2) { b3 = b2; k3 = k2; b2 = d; k2 = k; }
    else if (d < b3) { b3 = d; k3 = k; }
}
// merge two sorted top-3 lists (self & shfl partner), tie -> lower k
__device__ __forceinline__ void merge3(float& b1, float& b2, float& b3,
                                       int& k1, int& k2, int& k3,
                                       float o1, float o2, float o3,
                                       int j1, int j2, int j3) {
    float m1, m2, m3; int n1, n2, n3;
    if (ltk(b1, k1, o1, j1)) {
        m1 = b1; n1 = k1;
        if (ltk(b2, k2, o1, j1)) {
            m2 = b2; n2 = k2;
            if (ltk(b3, k3, o1, j1)) { m3 = b3; n3 = k3; } else { m3 = o1; n3 = j1; }
        } else {
            m2 = o1; n2 = j1;
            if (ltk(b2, k2, o2, j2)) { m3 = b2; n3 = k2; } else { m3 = o2; n3 = j2; }
        }
    } else {
        m1 = o1; n1 = j1;
        if (ltk(o2, j2, b1, k1)) {
            m2 = o2; n2 = j2;
            if (ltk(o3, j3, b1, k1)) { m3 = o3; n3 = j3; } else { m3 = b1; n3 = k1; }
        } else {
            m2 = b1; n2 = k1;
            if (ltk(o2, j2, b2, k2)) { m3 = o2; n3 = j2; } else { m3 = b2; n3 = k2; }
        }
    }
    b1 = m1; b2 = m2; b3 = m3; k1 = n1; k2 = n2; k3 = n3;
}

__global__ __launch_bounds__(NTHREADS) void kmeans_hmma_kernel(
    const float* __restrict__ x,
    const float* __restrict__ c,
    float* __restrict__ out_assign,
    int n, int ntiles)
{
    extern __shared__ char smem[];
    const uint32_t sb = smem_u32(smem);
    const int tid = threadIdx.x;
    const int lane = tid & 31;
    const int wid = tid >> 5;
    const int rows0 = wid * 32;
    float* csq_s = reinterpret_cast<float*>(smem + OFF_CSQ);

    // ---- one-time per CTA: csq (reference-identical rounding) + b = -2c bf16 split
    for (int k = tid; k < NK; k += NTHREADS) {
        const float4* cr = reinterpret_cast<const float4*>(c) + k * (ND / 4);
        float s0 = 0.f, s1 = 0.f, s2 = 0.f, s3 = 0.f;
#pragma unroll
        for (int j = 0; j < ND / 4; ++j) {
            float4 v = cr[j];
            s0 = fmaf(v.x, v.x, s0); s1 = fmaf(v.y, v.y, s1);
            s2 = fmaf(v.z, v.z, s2); s3 = fmaf(v.w, v.w, s3);
        }
        csq_s[k] = (s0 + s1) + (s2 + s3);
    }
    for (int idx = tid; idx < NK * ND / 2; idx += NTHREADS) {   // per bf16x2 pair
        int row = idx >> 5, d2 = idx & 31;
        float v0 = -2.0f * c[row * ND + d2 * 2];
        float v1 = -2.0f * c[row * ND + d2 * 2 + 1];
        __nv_bfloat16 h0 = __float2bfloat16(v0);
        __nv_bfloat16 l0 = __float2bfloat16(v0 - __bfloat162float(h0));
        __nv_bfloat16 h1 = __float2bfloat16(v1);
        __nv_bfloat16 l1 = __float2bfloat16(v1 - __bfloat162float(h1));
        uint32_t off = row * 128 + ((d2 * 4) ^ ((row & 7) << 4));
        *reinterpret_cast<__nv_bfloat162*>(smem + OFF_CHI + off) = __nv_bfloat162(h0, h1);
        *reinterpret_cast<__nv_bfloat162*>(smem + OFF_CLO + off) = __nv_bfloat162(l0, l1);
    }

    // per-lane ldmatrix address components
    const uint32_t aSwz = (uint32_t)(((lane >> 4) << 4) ^ ((lane & 7) << 4));
    const uint32_t aOffA = sb + OFF_XHI + (rows0 + (lane & 15)) * 128;
    const uint32_t loD = OFF_XLO - OFF_XHI;
    const uint32_t bSwz = (uint32_t)((((lane >> 3) & 1) << 4) ^ ((lane & 7) << 4));
    const uint32_t bOff = sb + OFF_CHI + (lane & 7) * 128;
    const uint32_t bLoD = OFF_CLO - OFF_CHI;

    for (int tile = blockIdx.x; tile < ntiles; tile += GRIDSZ) {
        __syncthreads();   // previous iteration's ldmatrix reads done before x overwrite

        // ---- stage x row 'tid' as bf16 hi/lo (zero-fill past n)
        const int p = tile * NTHREADS + tid;
        {
            float4 xr[16];
            if (p < n) {
                const float4* xrp = reinterpret_cast<const float4*>(x) + (size_t)p * (ND / 4);
#pragma unroll
                for (int j = 0; j < 16; ++j) xr[j] = __ldg(xrp + j);
            } else {
#pragma unroll
                for (int j = 0; j < 16; ++j) xr[j] = make_float4(0.f, 0.f, 0.f, 0.f);
            }
            const uint32_t rbase = tid * 128;
#pragma unroll
            for (int j = 0; j < 16; ++j) {
                float v[4] = { xr[j].x, xr[j].y, xr[j].z, xr[j].w };
#pragma unroll
                for (int q = 0; q < 2; ++q) {
                    float a0 = v[2 * q], a1 = v[2 * q + 1];
                    __nv_bfloat16 h0 = __float2bfloat16(a0);
                    __nv_bfloat16 l0 = __float2bfloat16(a0 - __bfloat162float(h0));
                    __nv_bfloat16 h1 = __float2bfloat16(a1);
                    __nv_bfloat16 l1 = __float2bfloat16(a1 - __bfloat162float(h1));
                    uint32_t off = rbase + (((j * 2 + q) * 4) ^ ((tid & 7) << 4));
                    *reinterpret_cast<__nv_bfloat162*>(smem + OFF_XHI + off) = __nv_bfloat162(h0, h1);
                    *reinterpret_cast<__nv_bfloat162*>(smem + OFF_XLO + off) = __nv_bfloat162(l0, l1);
                }
            }
        }
        __syncthreads();

        // ---- top-3 trackers: 4 row-slots per lane
        float b1[4], b2[4], b3[4]; int k1[4], k2[4], k3[4];
#pragma unroll
        for (int s = 0; s < 4; ++s) { b1[s] = b2[s] = b3[s] = 3.4e38f; k1[s] = k2[s] = k3[s] = 0; }

#pragma unroll 1
        for (int ch = 0; ch < 4; ++ch) {
            const int NB = ch * 64;
            float accA[8][4], accB[8][4];
#pragma unroll
            for (int nt = 0; nt < 8; ++nt) {
                float2 cs = *reinterpret_cast<const float2*>(&csq_s[NB + nt * 8 + ((lane & 3) << 1)]);
                accA[nt][0] = cs.x; accA[nt][1] = cs.y; accA[nt][2] = cs.x; accA[nt][3] = cs.y;
                accB[nt][0] = cs.x; accB[nt][1] = cs.y; accB[nt][2] = cs.x; accB[nt][3] = cs.y;
            }
#pragma unroll
            for (int kc = 0; kc < 4; ++kc) {
                const uint32_t ko = (uint32_t)(kc * 32) ^ aSwz;
                uint32_t AhA[4], AlA[4], AhB[4], AlB[4];
                ldsm_x4(AhA, aOffA + ko);
                ldsm_x4(AlA, aOffA + loD + ko);
                ldsm_x4(AhB, aOffA + 16 * 128 + ko);
                ldsm_x4(AlB, aOffA + loD + 16 * 128 + ko);
                const uint32_t kb = (uint32_t)(kc * 32) ^ bSwz;
#pragma unroll
                for (int nt = 0; nt < 8; ++nt) {
                    uint32_t bo = bOff + (uint32_t)((NB + nt * 8) * 128) + kb;
                    uint32_t bh[2], bl[2];
                    ldsm_x2(bh, bo);
                    ldsm_x2(bl, bo + bLoD);
                    mma16816(accA[nt], AhA, bh);
                    mma16816(accA[nt], AhA, bl);
                    mma16816(accA[nt], AlA, bh);
                    mma16816(accB[nt], AhB, bh);
                    mma16816(accB[nt], AhB, bl);
                    mma16816(accB[nt], AlB, bh);
                }
            }
            // fold chunk into top-3 (ascending k)
#pragma unroll
            for (int nt = 0; nt < 8; ++nt) {
                int c0 = NB + nt * 8 + ((lane & 3) << 1);
                upd3(accA[nt][0], c0,     b1[0], b2[0], b3[0], k1[0], k2[0], k3[0]);
                upd3(accA[nt][1], c0 + 1, b1[0], b2[0], b3[0], k1[0], k2[0], k3[0]);
                upd3(accA[nt][2], c0,     b1[1], b2[1], b3[1], k1[1], k2[1], k3[1]);
                upd3(accA[nt][3], c0 + 1, b1[1], b2[1], b3[1], k1[1], k2[1], k3[1]);
                upd3(accB[nt][0], c0,     b1[2], b2[2], b3[2], k1[2], k2[2], k3[2]);
                upd3(accB[nt][1], c0 + 1, b1[2], b2[2], b3[2], k1[2], k2[2], k3[2]);
                upd3(accB[nt][2], c0,     b1[3], b2[3], b3[3], k1[3], k2[3], k3[3]);
                upd3(accB[nt][3], c0 + 1, b1[3], b2[3], b3[3], k1[3], k2[3], k3[3]);
            }
        }

        // ---- quad merge (lanes 4g..4g+3 cover the same rows)
#pragma unroll
        for (int s = 0; s < 4; ++s) {
#pragma unroll
            for (int step = 1; step <= 2; step <<= 1) {
                float o1 = __shfl_xor_sync(0xFFFFFFFFu, b1[s], step);
                float o2 = __shfl_xor_sync(0xFFFFFFFFu, b2[s], step);
                float o3 = __shfl_xor_sync(0xFFFFFFFFu, b3[s], step);
                int j1 = __shfl_xor_sync(0xFFFFFFFFu, k1[s], step);
                int j2 = __shfl_xor_sync(0xFFFFFFFFu, k2[s], step);
                int j3 = __shfl_xor_sync(0xFFFFFFFFu, k3[s], step);
                merge3(b1[s], b2[s], b3[s], k1[s], k2[s], k3[s], o1, o2, o3, j1, j2, j3);
            }
        }

        // ---- refine + store (lane%4 == 0 owns 4 rows)
        if ((lane & 3) == 0) {
            const int g = lane >> 2;
#pragma unroll 1
            for (int s = 0; s < 4; ++s) {
                const int srow = rows0 + g + s * 8;   // s: +0, +8, +16, +24
                const int pp = tile * NTHREADS + srow;
                if (pp >= n) continue;
                int kbest = k1[s];
                if (b2[s] - b1[s] < THRESH) {
                    // candidate set, ascending k (first-occurrence ties like reference)
                    int ca[3]; int nc = 0;
                    ca[nc++] = k1[s]; ca[nc++] = k2[s];
                    if (b3[s] - b1[s] < THRESH) ca[nc++] = k3[s];
                    if (nc == 3) {
                        if (ca[0] > ca[1]) { int t = ca[0]; ca[0] = ca[1]; ca[1] = t; }
                        if (ca[1] > ca[2]) { int t = ca[1]; ca[1] = ca[2]; ca[2] = t; }
                        if (ca[0] > ca[1]) { int t = ca[0]; ca[0] = ca[1]; ca[1] = t; }
                    } else if (ca[0] > ca[1]) { int t = ca[0]; ca[0] = ca[1]; ca[1] = t; }
                    // exact fp32, reference-identical (validated rel_err=0 in rounds 1-4)
                    const float4* xrp = reinterpret_cast<const float4*>(x) + (size_t)pp * (ND / 4);
                    float4 xr[16];
#pragma unroll
                    for (int j = 0; j < 16; ++j) xr[j] = __ldg(xrp + j);
                    float s0 = 0.f, s1 = 0.f, s2 = 0.f, s3 = 0.f;
#pragma unroll
                    for (int j = 0; j < 16; ++j) {
                        s0 = fmaf(xr[j].x, xr[j].x, s0); s1 = fmaf(xr[j].y, xr[j].y, s1);
                        s2 = fmaf(xr[j].z, xr[j].z, s2); s3 = fmaf(xr[j].w, xr[j].w, s3);
                    }
                    const float xsq = (s0 + s1) + (s2 + s3);
                    float bd = 3.4e38f;
                    for (int i2 = 0; i2 < nc; ++i2) {
                        int kk = ca[i2];
                        const float4* cr = reinterpret_cast<const float4*>(c) + kk * (ND / 4);
                        float t0 = 0.f, t1 = 0.f, t2 = 0.f, t3 = 0.f;
#pragma unroll
                        for (int j = 0; j < 16; ++j) {
                            float4 cv = __ldg(cr + j);
                            t0 = fmaf(xr[j].x, cv.x, t0); t1 = fmaf(xr[j].y, cv.y, t1);
                            t2 = fmaf(xr[j].z, cv.z, t2); t3 = fmaf(xr[j].w, cv.w, t3);
                        }
                        float t = (t0 + t1) + (t2 + t3);
                        float d = fmaf(-2.0f, t, xsq) + csq_s[kk];
                        if (d < bd) { bd = d; kbest = kk; }
                    }
                }
                out_assign[pp] = (float)kbest;
            }
        }
    }
}

extern "C" void kernel_launch(void* const* d_in, const int* in_sizes, int n_in,
                              void* d_out, int out_size) {
    const float* x = (const float*)d_in[0];   // [N, 64]
    const float* c = (const float*)d_in[1];   // [256, 64]
    float* out = (float*)d_out;               // [256*64 centroids | N assignments]

    int n = in_sizes[0] / ND;
    int ntiles = (n + NTHREADS - 1) / NTHREADS;

    cudaMemcpyAsync(out, c, (size_t)NK * ND * sizeof(float),
                    cudaMemcpyDeviceToDevice, 0);

    cudaFuncSetAttribute(kmeans_hmma_kernel,
                         cudaFuncAttributeMaxDynamicSharedMemorySize, SMEM_TOTAL);
    kmeans_hmma_kernel<<<GRIDSZ, NTHREADS, SMEM_TOTAL>>>(x, c, out + NK * ND, n, ntiles);
}

// round 10
// speedup vs baseline: 3.0088x; 3.0088x over previous
#include <cuda_runtime.h>
#include <cuda_bf16.h>
#include <cstdint>

#define NK 256
#define ND 64
#define NTHREADS 128
#define GRIDSZ 296
// Accumulators are biased by +1024 so every packed value is a positive float
// (raw d = csq - 2x.c is often negative; unsigned-bit compare requires > 0).
// At |value| ~ 1024, dropping 8 mantissa bits quantizes at ~0.031, so the
// refine band must cover ~2x that plus the bf16-split error:
#define BIAS 1024.0f
#define THRESH 0.08f

// smem layout (tile bases 1024-aligned; swizzle is within each 128B row)
#define OFF_CSQ 0                       // 256 f32
#define OFF_CHI 1024                    // 256 x 128B bf16 (hi of -2c), swizzled
#define OFF_CLO (OFF_CHI + 32768)
#define OFF_XHI (OFF_CLO + 32768)       // 128 x 128B
#define OFF_XLO (OFF_XHI + 16384)
#define SMEM_TOTAL (OFF_XLO + 16384)    // 99328 B

__device__ __forceinline__ uint32_t smem_u32(const void* p) {
    uint32_t a;
    asm("{ .reg .u64 t; cvta.to.shared.u64 t, %1; cvt.u32.u64 %0, t; }" : "=r"(a) : "l"(p));
    return a;
}
__device__ __forceinline__ void ldsm_x4(uint32_t a[4], uint32_t addr) {
    asm volatile("ldmatrix.sync.aligned.m8n8.x4.shared.b16 {%0,%1,%2,%3}, [%4];"
        : "=r"(a[0]), "=r"(a[1]), "=r"(a[2]), "=r"(a[3]) : "r"(addr));
}
__device__ __forceinline__ void mma2(float c[4], const uint32_t a[4], uint32_t b0, uint32_t b1) {
    asm volatile("mma.sync.aligned.m16n8k16.row.col.f32.bf16.bf16.f32 "
        "{%0,%1,%2,%3}, {%4,%5,%6,%7}, {%8,%9}, {%0,%1,%2,%3};"
        : "+f"(c[0]), "+f"(c[1]), "+f"(c[2]), "+f"(c[3])
        : "r"(a[0]), "r"(a[1]), "r"(a[2]), "r"(a[3]), "r"(b0), "r"(b1));
}
// packed (dist,k): high 24 bits of POSITIVE float dist, low 8 bits k.
// unsigned compare == (dist-trunc, k) lexicographic -> min == first-occurrence argmin.
__device__ __forceinline__ void upd_packed(uint32_t& m1, uint32_t& m2, uint32_t& m3,
                                           float d, uint32_t k) {
    uint32_t u = (__float_as_uint(d) & 0xFFFFFF00u) | k;   // one LOP3
    uint32_t t1 = max(u, m1);  m1 = min(u, m1);
    uint32_t t2 = max(t1, m2); m2 = min(t1, m2);
    m3 = min(t2, m3);
}

__global__ __launch_bounds__(NTHREADS, 2) void kmeans_hmma_kernel(
    const float* __restrict__ x,
    const float* __restrict__ c,
    float* __restrict__ out_assign,
    int n, int ntiles)
{
    extern __shared__ char smem[];
    const uint32_t sb = smem_u32(smem);
    const int tid = threadIdx.x;
    const int lane = tid & 31;
    const int wid = tid >> 5;
    const int rows0 = wid * 32;
    float* csq_s = reinterpret_cast<float*>(smem + OFF_CSQ);

    // ---- one-time: csq (reference-identical rounding) + bf16-split of -2c, STS.128
    for (int k = tid; k < NK; k += NTHREADS) {
        const float4* cr = reinterpret_cast<const float4*>(c) + k * (ND / 4);
        float s0 = 0.f, s1 = 0.f, s2 = 0.f, s3 = 0.f;
#pragma unroll
        for (int j = 0; j < ND / 4; ++j) {
            float4 v = cr[j];
            s0 = fmaf(v.x, v.x, s0); s1 = fmaf(v.y, v.y, s1);
            s2 = fmaf(v.z, v.z, s2); s3 = fmaf(v.w, v.w, s3);
        }
        csq_s[k] = (s0 + s1) + (s2 + s3);
    }
    for (int idx = tid; idx < NK * 8; idx += NTHREADS) {      // one 16B chunk (8 dims)
        int row = idx >> 3, jj = idx & 7;
        const float4* cp = reinterpret_cast<const float4*>(c) + row * (ND / 4) + jj * 2;
        float4 va = cp[0], vb = cp[1];
        float v[8] = { -2.f*va.x, -2.f*va.y, -2.f*va.z, -2.f*va.w,
                       -2.f*vb.x, -2.f*vb.y, -2.f*vb.z, -2.f*vb.w };
        uint32_t hw[4], lw[4];
#pragma unroll
        for (int q = 0; q < 4; ++q) {
            __nv_bfloat162 h = __floats2bfloat162_rn(v[2*q], v[2*q+1]);
            __nv_bfloat162 l = __floats2bfloat162_rn(v[2*q]   - __low2float(h),
                                                     v[2*q+1] - __high2float(h));
            hw[q] = *reinterpret_cast<uint32_t*>(&h);
            lw[q] = *reinterpret_cast<uint32_t*>(&l);
        }
        uint32_t off = row * 128 + ((jj * 16) ^ ((row & 7) << 4));
        *reinterpret_cast<uint4*>(smem + OFF_CHI + off) = make_uint4(hw[0], hw[1], hw[2], hw[3]);
        *reinterpret_cast<uint4*>(smem + OFF_CLO + off) = make_uint4(lw[0], lw[1], lw[2], lw[3]);
    }

    // ---- per-lane ldmatrix addressing (A pattern verified correct in round 6)
    const uint32_t aSwz = (uint32_t)(((lane >> 4) << 4) ^ ((lane & 7) << 4));
    const uint32_t aHiBase = sb + OFF_XHI + (rows0 + (lane & 15)) * 128;
    const uint32_t loD = OFF_XLO - OFF_XHI;
    // B x4: lane-groups -> mats (n0-7,k0)(n0-7,k8)(n8-15,k0)(n8-15,k8) per 16-row pair
    const uint32_t bRowL = ((lane >> 4) & 1) * 8 + (lane & 7);
    const uint32_t bKbit = ((lane >> 3) & 1) << 4;
    const uint32_t bSwzL = (lane & 7) << 4;                  // = (bRowL & 7) << 4
    const uint32_t bHiBase = sb + OFF_CHI + bRowL * 128;
    const uint32_t bLoD = OFF_CLO - OFF_CHI;

    const uint32_t wswz = (uint32_t)((tid & 7) << 4);
    const uint32_t rbase = (uint32_t)tid * 128;

    for (int tile = blockIdx.x; tile < ntiles; tile += GRIDSZ) {
        // ---- issue x loads for THIS tile before the barrier (overlap with sync wait)
        const int p = tile * NTHREADS + tid;
        float4 xr[16];
        if (p < n) {
            const float4* xrp = reinterpret_cast<const float4*>(x) + (size_t)p * (ND / 4);
#pragma unroll
            for (int j = 0; j < 16; ++j) xr[j] = __ldg(xrp + j);
        } else {
#pragma unroll
            for (int j = 0; j < 16; ++j) xr[j] = make_float4(0.f, 0.f, 0.f, 0.f);
        }
        // L2 prefetch of next tile's x, one iteration ahead (clamped in-bounds)
        if (tile + GRIDSZ < ntiles) {
            int pidx = (tile + GRIDSZ) * NTHREADS + tid;
            if (pidx > n - 1) pidx = n - 1;
            const float* nx = x + (size_t)pidx * ND;
            asm volatile("prefetch.global.L2 [%0];" :: "l"(nx));
            asm volatile("prefetch.global.L2 [%0];" :: "l"(nx + 32));
        }

        __syncthreads();    // prior iteration's ldsm reads complete before overwrite

        // ---- stage x row 'tid' as bf16 hi/lo via STS.128
#pragma unroll
        for (int jj = 0; jj < 8; ++jj) {
            float v[8] = { xr[2*jj].x, xr[2*jj].y, xr[2*jj].z, xr[2*jj].w,
                           xr[2*jj+1].x, xr[2*jj+1].y, xr[2*jj+1].z, xr[2*jj+1].w };
            uint32_t hw[4], lw[4];
#pragma unroll
            for (int q = 0; q < 4; ++q) {
                __nv_bfloat162 h = __floats2bfloat162_rn(v[2*q], v[2*q+1]);
                __nv_bfloat162 l = __floats2bfloat162_rn(v[2*q]   - __low2float(h),
                                                         v[2*q+1] - __high2float(h));
                hw[q] = *reinterpret_cast<uint32_t*>(&h);
                lw[q] = *reinterpret_cast<uint32_t*>(&l);
            }
            uint32_t off = rbase + ((jj * 16) ^ wswz);
            *reinterpret_cast<uint4*>(smem + OFF_XHI + off) = make_uint4(hw[0], hw[1], hw[2], hw[3]);
            *reinterpret_cast<uint4*>(smem + OFF_XLO + off) = make_uint4(lw[0], lw[1], lw[2], lw[3]);
        }
        __syncthreads();

        // ---- packed top-3 per slot (4 point-rows per lane)
        uint32_t M1[4], M2[4], M3[4];
#pragma unroll
        for (int s = 0; s < 4; ++s) { M1[s] = M2[s] = M3[s] = 0xFFFFFFFFu; }

#pragma unroll 1
        for (int ch = 0; ch < 4; ++ch) {
            const int NB = ch * 64;
            const int cbase = NB + ((lane & 3) << 1);
            float accA[8][4], accB[8][4];
#pragma unroll
            for (int nt = 0; nt < 8; ++nt) {
                float2 cs = *reinterpret_cast<const float2*>(&csq_s[cbase + nt * 8]);
                float c0b = cs.x + BIAS, c1b = cs.y + BIAS;   // positivity bias
                accA[nt][0] = c0b; accA[nt][1] = c1b; accA[nt][2] = c0b; accA[nt][3] = c1b;
                accB[nt][0] = c0b; accB[nt][1] = c1b; accB[nt][2] = c0b; accB[nt][3] = c1b;
            }
#pragma unroll
            for (int kc = 0; kc < 4; ++kc) {
                const uint32_t ak = (uint32_t)(kc * 32) ^ aSwz;
                const uint32_t bk = (uint32_t)(kc * 32 + bKbit) ^ bSwzL;
                const uint32_t bb = bHiBase + (uint32_t)(ch * 8192) + bk;
                uint32_t AhA[4], AlA[4], AhB[4], AlB[4];
                uint32_t Bh[4][4], Bl[4][4];
                // all loads up front: latency pipelined across 12 ldsm
                ldsm_x4(AhA, aHiBase + ak);
                ldsm_x4(AhB, aHiBase + 16 * 128 + ak);
                ldsm_x4(Bh[0], bb);
                ldsm_x4(Bh[1], bb + 2048);
                ldsm_x4(Bh[2], bb + 4096);
                ldsm_x4(Bh[3], bb + 6144);
                ldsm_x4(AlA, aHiBase + loD + ak);
                ldsm_x4(AlB, aHiBase + loD + 16 * 128 + ak);
                ldsm_x4(Bl[0], bb + bLoD);
                ldsm_x4(Bl[1], bb + bLoD + 2048);
                ldsm_x4(Bl[2], bb + bLoD + 4096);
                ldsm_x4(Bl[3], bb + bLoD + 6144);
                // 96 MMAs, same acc revisited only every 16 instructions
#pragma unroll
                for (int nt = 0; nt < 8; ++nt)
                    mma2(accA[nt], AhA, Bh[nt >> 1][(nt & 1) * 2], Bh[nt >> 1][(nt & 1) * 2 + 1]);
#pragma unroll
                for (int nt = 0; nt < 8; ++nt)
                    mma2(accB[nt], AhB, Bh[nt >> 1][(nt & 1) * 2], Bh[nt >> 1][(nt & 1) * 2 + 1]);
#pragma unroll
                for (int nt = 0; nt < 8; ++nt)
                    mma2(accA[nt], AhA, Bl[nt >> 1][(nt & 1) * 2], Bl[nt >> 1][(nt & 1) * 2 + 1]);
#pragma unroll
                for (int nt = 0; nt < 8; ++nt)
                    mma2(accB[nt], AhB, Bl[nt >> 1][(nt & 1) * 2], Bl[nt >> 1][(nt & 1) * 2 + 1]);
#pragma unroll
                for (int nt = 0; nt < 8; ++nt)
                    mma2(accA[nt], AlA, Bh[nt >> 1][(nt & 1) * 2], Bh[nt >> 1][(nt & 1) * 2 + 1]);
#pragma unroll
                for (int nt = 0; nt < 8; ++nt)
                    mma2(accB[nt], AlB, Bh[nt >> 1][(nt & 1) * 2], Bh[nt >> 1][(nt & 1) * 2 + 1]);
            }
            // branchless fold into packed top-3 (all values positive after bias)
#pragma unroll
            for (int nt = 0; nt < 8; ++nt) {
                uint32_t c0 = (uint32_t)(cbase + nt * 8);
                upd_packed(M1[0], M2[0], M3[0], accA[nt][0], c0);
                upd_packed(M1[0], M2[0], M3[0], accA[nt][1], c0 + 1);
                upd_packed(M1[1], M2[1], M3[1], accA[nt][2], c0);
                upd_packed(M1[1], M2[1], M3[1], accA[nt][3], c0 + 1);
                upd_packed(M1[2], M2[2], M3[2], accB[nt][0], c0);
                upd_packed(M1[2], M2[2], M3[2], accB[nt][1], c0 + 1);
                upd_packed(M1[3], M2[3], M3[3], accB[nt][2], c0);
                upd_packed(M1[3], M2[3], M3[3], accB[nt][3], c0 + 1);
            }
        }

        // ---- quad merge (sorted top-3 union via min/max network)
#pragma unroll
        for (int s = 0; s < 4; ++s) {
#pragma unroll
            for (int step = 1; step <= 2; step <<= 1) {
                uint32_t o1 = __shfl_xor_sync(0xFFFFFFFFu, M1[s], step);
                uint32_t o2 = __shfl_xor_sync(0xFFFFFFFFu, M2[s], step);
                uint32_t o3 = __shfl_xor_sync(0xFFFFFFFFu, M3[s], step);
                uint32_t pm = max(M1[s], o1);
                M1[s] = min(M1[s], o1);
                uint32_t qm = min(M2[s], o2);
                M3[s] = min(max(pm, qm), min(M3[s], o3));
                M2[s] = min(pm, qm);
            }
        }

        // ---- refine + store (lane%4 == 0 owns rows g, g+8, g+16, g+24)
        if ((lane & 3) == 0) {
            const int g = lane >> 2;
#pragma unroll 1
            for (int s = 0; s < 4; ++s) {
                const int pp = tile * NTHREADS + rows0 + g + s * 8;
                if (pp >= n) continue;
                int kbest = (int)(M1[s] & 0xFFu);
                float d1 = __uint_as_float(M1[s] & 0xFFFFFF00u);   // biased; bias cancels in gaps
                float d2 = __uint_as_float(M2[s] & 0xFFFFFF00u);
                if (d2 - d1 < THRESH) {
                    float d3 = __uint_as_float(M3[s] & 0xFFFFFF00u);
                    int ca[3]; int nc = 0;
                    ca[nc++] = (int)(M1[s] & 0xFFu);
                    ca[nc++] = (int)(M2[s] & 0xFFu);
                    if (d3 - d1 < THRESH) ca[nc++] = (int)(M3[s] & 0xFFu);
                    if (nc == 3) {
                        if (ca[0] > ca[1]) { int t = ca[0]; ca[0] = ca[1]; ca[1] = t; }
                        if (ca[1] > ca[2]) { int t = ca[1]; ca[1] = ca[2]; ca[2] = t; }
                        if (ca[0] > ca[1]) { int t = ca[0]; ca[0] = ca[1]; ca[1] = t; }
                    } else if (ca[0] > ca[1]) { int t = ca[0]; ca[0] = ca[1]; ca[1] = t; }
                    // exact fp32, reference-identical (rel_err 0.0 in rounds 1-4, 6)
                    const float4* xrp = reinterpret_cast<const float4*>(x) + (size_t)pp * (ND / 4);
                    float4 xq[16];
#pragma unroll
                    for (int j = 0; j < 16; ++j) xq[j] = __ldg(xrp + j);
                    float s0 = 0.f, s1 = 0.f, s2 = 0.f, s3 = 0.f;
#pragma unroll
                    for (int j = 0; j < 16; ++j) {
                        s0 = fmaf(xq[j].x, xq[j].x, s0); s1 = fmaf(xq[j].y, xq[j].y, s1);
                        s2 = fmaf(xq[j].z, xq[j].z, s2); s3 = fmaf(xq[j].w, xq[j].w, s3);
                    }
                    const float xsq = (s0 + s1) + (s2 + s3);
                    float bd = 3.4e38f;
                    for (int i2 = 0; i2 < nc; ++i2) {
                        int kk = ca[i2];
                        const float4* cr = reinterpret_cast<const float4*>(c) + kk * (ND / 4);
                        float t0 = 0.f, t1 = 0.f, t2 = 0.f, t3 = 0.f;
#pragma unroll
                        for (int j = 0; j < 16; ++j) {
                            float4 cv = __ldg(cr + j);
                            t0 = fmaf(xq[j].x, cv.x, t0); t1 = fmaf(xq[j].y, cv.y, t1);
                            t2 = fmaf(xq[j].z, cv.z, t2); t3 = fmaf(xq[j].w, cv.w, t3);
                        }
                        float t = (t0 + t1) + (t2 + t3);
                        float d = fmaf(-2.0f, t, xsq) + csq_s[kk];
                        if (d < bd) { bd = d; kbest = kk; }
                    }
                }
                out_assign[pp] = (float)kbest;
            }
        }
    }
}

extern "C" void kernel_launch(void* const* d_in, const int* in_sizes, int n_in,
                              void* d_out, int out_size) {
    const float* x = (const float*)d_in[0];   // [N, 64]
    const float* c = (const float*)d_in[1];   // [256, 64]
    float* out = (float*)d_out;               // [256*64 centroids | N assignments]

    int n = in_sizes[0] / ND;
    int ntiles = (n + NTHREADS - 1) / NTHREADS;

    cudaMemcpyAsync(out, c, (size_t)NK * ND * sizeof(float),
                    cudaMemcpyDeviceToDevice, 0);

    cudaFuncSetAttribute(kmeans_hmma_kernel,
                         cudaFuncAttributeMaxDynamicSharedMemorySize, SMEM_TOTAL);
    kmeans_hmma_kernel<<<GRIDSZ, NTHREADS, SMEM_TOTAL>>>(x, c, out + NK * ND, n, ntiles);
}

// round 11
// speedup vs baseline: 3.4044x; 1.1315x over previous
#include <cuda_runtime.h>
#include <cuda_bf16.h>
#include <cstdint>

#define NK 256
#define ND 64
#define NTHREADS 128
#define GRIDSZ 296
// Accumulators biased +1024 so every packed value is a positive float
// (unsigned-bit compare valid only for positive floats). Guard band now
// covers: 2x 8-bit-mantissa truncation at |d|~1024 (0.062) + dropped
// x_lo*b GEMM term (5 sigma ~ 0.05) + kept-split residual:
#define BIAS 1024.0f
#define THRESH 0.16f

// smem layout (tile bases 1024-aligned; swizzle within each 128B row)
#define OFF_CSQ 0                       // 256 f32
#define OFF_CHI 1024                    // 256 x 128B bf16 (hi of -2c), swizzled
#define OFF_CLO (OFF_CHI + 32768)
#define OFF_XHI (OFF_CLO + 32768)       // 128 x 128B (x_hi only; no x_lo tile)
#define SMEM_TOTAL (OFF_XHI + 16384)    // 82944 B

__device__ __forceinline__ uint32_t smem_u32(const void* p) {
    uint32_t a;
    asm("{ .reg .u64 t; cvta.to.shared.u64 t, %1; cvt.u32.u64 %0, t; }" : "=r"(a) : "l"(p));
    return a;
}
__device__ __forceinline__ void ldsm_x4(uint32_t a[4], uint32_t addr) {
    asm volatile("ldmatrix.sync.aligned.m8n8.x4.shared.b16 {%0,%1,%2,%3}, [%4];"
        : "=r"(a[0]), "=r"(a[1]), "=r"(a[2]), "=r"(a[3]) : "r"(addr));
}
__device__ __forceinline__ void mma2(float c[4], const uint32_t a[4], uint32_t b0, uint32_t b1) {
    asm volatile("mma.sync.aligned.m16n8k16.row.col.f32.bf16.bf16.f32 "
        "{%0,%1,%2,%3}, {%4,%5,%6,%7}, {%8,%9}, {%0,%1,%2,%3};"
        : "+f"(c[0]), "+f"(c[1]), "+f"(c[2]), "+f"(c[3])
        : "r"(a[0]), "r"(a[1]), "r"(a[2]), "r"(a[3]), "r"(b0), "r"(b1));
}
// packed (dist,k): high 24 bits of POSITIVE float dist, low 8 bits k.
// unsigned compare == (dist-trunc, k) lexicographic -> min == first-occurrence argmin.
__device__ __forceinline__ void upd_packed(uint32_t& m1, uint32_t& m2, uint32_t& m3,
                                           float d, uint32_t k) {
    uint32_t u = (__float_as_uint(d) & 0xFFFFFF00u) | k;   // one LOP3
    uint32_t t1 = max(u, m1);  m1 = min(u, m1);
    uint32_t t2 = max(t1, m2); m2 = min(t1, m2);
    m3 = min(t2, m3);
}

__global__ __launch_bounds__(NTHREADS, 2) void kmeans_hmma_kernel(
    const float* __restrict__ x,
    const float* __restrict__ c,
    float* __restrict__ out_assign,
    int n, int ntiles)
{
    extern __shared__ char smem[];
    const uint32_t sb = smem_u32(smem);
    const int tid = threadIdx.x;
    const int lane = tid & 31;
    const int wid = tid >> 5;
    const int rows0 = wid * 32;
    float* csq_s = reinterpret_cast<float*>(smem + OFF_CSQ);

    // ---- one-time: csq (reference-identical rounding) + bf16-split of -2c, STS.128
    for (int k = tid; k < NK; k += NTHREADS) {
        const float4* cr = reinterpret_cast<const float4*>(c) + k * (ND / 4);
        float s0 = 0.f, s1 = 0.f, s2 = 0.f, s3 = 0.f;
#pragma unroll
        for (int j = 0; j < ND / 4; ++j) {
            float4 v = cr[j];
            s0 = fmaf(v.x, v.x, s0); s1 = fmaf(v.y, v.y, s1);
            s2 = fmaf(v.z, v.z, s2); s3 = fmaf(v.w, v.w, s3);
        }
        csq_s[k] = (s0 + s1) + (s2 + s3);
    }
    for (int idx = tid; idx < NK * 8; idx += NTHREADS) {      // one 16B chunk (8 dims)
        int row = idx >> 3, jj = idx & 7;
        const float4* cp = reinterpret_cast<const float4*>(c) + row * (ND / 4) + jj * 2;
        float4 va = cp[0], vb = cp[1];
        float v[8] = { -2.f*va.x, -2.f*va.y, -2.f*va.z, -2.f*va.w,
                       -2.f*vb.x, -2.f*vb.y, -2.f*vb.z, -2.f*vb.w };
        uint32_t hw[4], lw[4];
#pragma unroll
        for (int q = 0; q < 4; ++q) {
            __nv_bfloat162 h = __floats2bfloat162_rn(v[2*q], v[2*q+1]);
            __nv_bfloat162 l = __floats2bfloat162_rn(v[2*q]   - __low2float(h),
                                                     v[2*q+1] - __high2float(h));
            hw[q] = *reinterpret_cast<uint32_t*>(&h);
            lw[q] = *reinterpret_cast<uint32_t*>(&l);
        }
        uint32_t off = row * 128 + ((jj * 16) ^ ((row & 7) << 4));
        *reinterpret_cast<uint4*>(smem + OFF_CHI + off) = make_uint4(hw[0], hw[1], hw[2], hw[3]);
        *reinterpret_cast<uint4*>(smem + OFF_CLO + off) = make_uint4(lw[0], lw[1], lw[2], lw[3]);
    }

    // ---- per-lane ldmatrix addressing (patterns validated rounds 6/10)
    const uint32_t aSwz = (uint32_t)(((lane >> 4) << 4) ^ ((lane & 7) << 4));
    const uint32_t aHiBase = sb + OFF_XHI + (rows0 + (lane & 15)) * 128;
    // B x4: lane-groups -> mats (n0-7,k0)(n0-7,k8)(n8-15,k0)(n8-15,k8) per 16-row pair
    const uint32_t bRowL = ((lane >> 4) & 1) * 8 + (lane & 7);
    const uint32_t bKbit = ((lane >> 3) & 1) << 4;
    const uint32_t bSwzL = (lane & 7) << 4;
    const uint32_t bHiBase = sb + OFF_CHI + bRowL * 128;
    const uint32_t bLoD = OFF_CLO - OFF_CHI;

    const uint32_t wswz = (uint32_t)((tid & 7) << 4);
    const uint32_t rbase = (uint32_t)tid * 128;

    for (int tile = blockIdx.x; tile < ntiles; tile += GRIDSZ) {
        // ---- issue x loads for THIS tile before the barrier
        const int p = tile * NTHREADS + tid;
        float4 xr[16];
        if (p < n) {
            const float4* xrp = reinterpret_cast<const float4*>(x) + (size_t)p * (ND / 4);
#pragma unroll
            for (int j = 0; j < 16; ++j) xr[j] = __ldg(xrp + j);
        } else {
#pragma unroll
            for (int j = 0; j < 16; ++j) xr[j] = make_float4(0.f, 0.f, 0.f, 0.f);
        }
        // L2 prefetch of next tile's x, one iteration ahead (clamped in-bounds)
        if (tile + GRIDSZ < ntiles) {
            int pidx = (tile + GRIDSZ) * NTHREADS + tid;
            if (pidx > n - 1) pidx = n - 1;
            const float* nx = x + (size_t)pidx * ND;
            asm volatile("prefetch.global.L2 [%0];" :: "l"(nx));
            asm volatile("prefetch.global.L2 [%0];" :: "l"(nx + 32));
        }

        __syncthreads();    // prior iteration's ldsm reads complete before overwrite

        // ---- stage x row 'tid' as bf16 HI ONLY via STS.128 (x_lo term dropped)
#pragma unroll
        for (int jj = 0; jj < 8; ++jj) {
            float v[8] = { xr[2*jj].x, xr[2*jj].y, xr[2*jj].z, xr[2*jj].w,
                           xr[2*jj+1].x, xr[2*jj+1].y, xr[2*jj+1].z, xr[2*jj+1].w };
            uint32_t hw[4];
#pragma unroll
            for (int q = 0; q < 4; ++q) {
                __nv_bfloat162 h = __floats2bfloat162_rn(v[2*q], v[2*q+1]);
                hw[q] = *reinterpret_cast<uint32_t*>(&h);
            }
            uint32_t off = rbase + ((jj * 16) ^ wswz);
            *reinterpret_cast<uint4*>(smem + OFF_XHI + off) = make_uint4(hw[0], hw[1], hw[2], hw[3]);
        }
        __syncthreads();

        // ---- packed top-3 per slot (4 point-rows per lane)
        uint32_t M1[4], M2[4], M3[4];
#pragma unroll
        for (int s = 0; s < 4; ++s) { M1[s] = M2[s] = M3[s] = 0xFFFFFFFFu; }

#pragma unroll 1
        for (int ch = 0; ch < 4; ++ch) {
            const int cbase = ch * 64 + ((lane & 3) << 1);
            float accA[8][4], accB[8][4];
#pragma unroll
            for (int nt = 0; nt < 8; ++nt) {
                float2 cs = *reinterpret_cast<const float2*>(&csq_s[cbase + nt * 8]);
                float c0b = cs.x + BIAS, c1b = cs.y + BIAS;   // positivity bias
                accA[nt][0] = c0b; accA[nt][1] = c1b; accA[nt][2] = c0b; accA[nt][3] = c1b;
                accB[nt][0] = c0b; accB[nt][1] = c1b; accB[nt][2] = c0b; accB[nt][3] = c1b;
            }
#pragma unroll
            for (int kc = 0; kc < 4; ++kc) {
                const uint32_t ak = (uint32_t)(kc * 32) ^ aSwz;
                const uint32_t bk = (uint32_t)(kc * 32 + bKbit) ^ bSwzL;
                const uint32_t bb = bHiBase + (uint32_t)(ch * 8192) + bk;
                uint32_t AhA[4], AhB[4];
                uint32_t Bh[4][4], Bl[4][4];
                // all 10 ldsm up front: latency pipelined
                ldsm_x4(AhA, aHiBase + ak);
                ldsm_x4(AhB, aHiBase + 16 * 128 + ak);
                ldsm_x4(Bh[0], bb);
                ldsm_x4(Bh[1], bb + 2048);
                ldsm_x4(Bh[2], bb + 4096);
                ldsm_x4(Bh[3], bb + 6144);
                ldsm_x4(Bl[0], bb + bLoD);
                ldsm_x4(Bl[1], bb + bLoD + 2048);
                ldsm_x4(Bl[2], bb + bLoD + 4096);
                ldsm_x4(Bl[3], bb + bLoD + 6144);
                // 32 MMAs (2 terms), same acc revisited only every 16 instructions
#pragma unroll
                for (int nt = 0; nt < 8; ++nt)
                    mma2(accA[nt], AhA, Bh[nt >> 1][(nt & 1) * 2], Bh[nt >> 1][(nt & 1) * 2 + 1]);
#pragma unroll
                for (int nt = 0; nt < 8; ++nt)
                    mma2(accB[nt], AhB, Bh[nt >> 1][(nt & 1) * 2], Bh[nt >> 1][(nt & 1) * 2 + 1]);
#pragma unroll
                for (int nt = 0; nt < 8; ++nt)
                    mma2(accA[nt], AhA, Bl[nt >> 1][(nt & 1) * 2], Bl[nt >> 1][(nt & 1) * 2 + 1]);
#pragma unroll
                for (int nt = 0; nt < 8; ++nt)
                    mma2(accB[nt], AhB, Bl[nt >> 1][(nt & 1) * 2], Bl[nt >> 1][(nt & 1) * 2 + 1]);
            }
            // branchless fold into packed top-3 (all values positive after bias)
#pragma unroll
            for (int nt = 0; nt < 8; ++nt) {
                uint32_t c0 = (uint32_t)(cbase + nt * 8);
                upd_packed(M1[0], M2[0], M3[0], accA[nt][0], c0);
                upd_packed(M1[0], M2[0], M3[0], accA[nt][1], c0 + 1);
                upd_packed(M1[1], M2[1], M3[1], accA[nt][2], c0);
                upd_packed(M1[1], M2[1], M3[1], accA[nt][3], c0 + 1);
                upd_packed(M1[2], M2[2], M3[2], accB[nt][0], c0);
                upd_packed(M1[2], M2[2], M3[2], accB[nt][1], c0 + 1);
                upd_packed(M1[3], M2[3], M3[3], accB[nt][2], c0);
                upd_packed(M1[3], M2[3], M3[3], accB[nt][3], c0 + 1);
            }
        }

        // ---- quad merge (sorted top-3 union via min/max network)
#pragma unroll
        for (int s = 0; s < 4; ++s) {
#pragma unroll
            for (int step = 1; step <= 2; step <<= 1) {
                uint32_t o1 = __shfl_xor_sync(0xFFFFFFFFu, M1[s], step);
                uint32_t o2 = __shfl_xor_sync(0xFFFFFFFFu, M2[s], step);
                uint32_t o3 = __shfl_xor_sync(0xFFFFFFFFu, M3[s], step);
                uint32_t pm = max(M1[s], o1);
                M1[s] = min(M1[s], o1);
                uint32_t qm = min(M2[s], o2);
                M3[s] = min(max(pm, qm), min(M3[s], o3));
                M2[s] = min(pm, qm);
            }
        }

        // ---- refine + store (lane%4 == 0 owns rows g, g+8, g+16, g+24)
        if ((lane & 3) == 0) {
            const int g = lane >> 2;
#pragma unroll 1
            for (int s = 0; s < 4; ++s) {
                const int pp = tile * NTHREADS + rows0 + g + s * 8;
                if (pp >= n) continue;
                int kbest = (int)(M1[s] & 0xFFu);
                float d1 = __uint_as_float(M1[s] & 0xFFFFFF00u);   // biased; cancels in gaps
                float d2 = __uint_as_float(M2[s] & 0xFFFFFF00u);
                if (d2 - d1 < THRESH) {
                    float d3 = __uint_as_float(M3[s] & 0xFFFFFF00u);
                    int ca[3]; int nc = 0;
                    ca[nc++] = (int)(M1[s] & 0xFFu);
                    ca[nc++] = (int)(M2[s] & 0xFFu);
                    if (d3 - d1 < THRESH) ca[nc++] = (int)(M3[s] & 0xFFu);
                    if (nc == 3) {
                        if (ca[0] > ca[1]) { int t = ca[0]; ca[0] = ca[1]; ca[1] = t; }
                        if (ca[1] > ca[2]) { int t = ca[1]; ca[1] = ca[2]; ca[2] = t; }
                        if (ca[0] > ca[1]) { int t = ca[0]; ca[0] = ca[1]; ca[1] = t; }
                    } else if (ca[0] > ca[1]) { int t = ca[0]; ca[0] = ca[1]; ca[1] = t; }
                    // exact fp32, reference-identical (rel_err 0.0 in rounds 1-4, 6, 10)
                    const float4* xrp = reinterpret_cast<const float4*>(x) + (size_t)pp * (ND / 4);
                    float4 xq[16];
#pragma unroll
                    for (int j = 0; j < 16; ++j) xq[j] = __ldg(xrp + j);
                    float s0 = 0.f, s1 = 0.f, s2 = 0.f, s3 = 0.f;
#pragma unroll
                    for (int j = 0; j < 16; ++j) {
                        s0 = fmaf(xq[j].x, xq[j].x, s0); s1 = fmaf(xq[j].y, xq[j].y, s1);
                        s2 = fmaf(xq[j].z, xq[j].z, s2); s3 = fmaf(xq[j].w, xq[j].w, s3);
                    }
                    const float xsq = (s0 + s1) + (s2 + s3);
                    float bd = 3.4e38f;
                    for (int i2 = 0; i2 < nc; ++i2) {
                        int kk = ca[i2];
                        const float4* cr = reinterpret_cast<const float4*>(c) + kk * (ND / 4);
                        float t0 = 0.f, t1 = 0.f, t2 = 0.f, t3 = 0.f;
#pragma unroll
                        for (int j = 0; j < 16; ++j) {
                            float4 cv = __ldg(cr + j);
                            t0 = fmaf(xq[j].x, cv.x, t0); t1 = fmaf(xq[j].y, cv.y, t1);
                            t2 = fmaf(xq[j].z, cv.z, t2); t3 = fmaf(xq[j].w, cv.w, t3);
                        }
                        float t = (t0 + t1) + (t2 + t3);
                        float d = fmaf(-2.0f, t, xsq) + csq_s[kk];
                        if (d < bd) { bd = d; kbest = kk; }
                    }
                }
                out_assign[pp] = (float)kbest;
            }
        }
    }
}

extern "C" void kernel_launch(void* const* d_in, const int* in_sizes, int n_in,
                              void* d_out, int out_size) {
    const float* x = (const float*)d_in[0];   // [N, 64]
    const float* c = (const float*)d_in[1];   // [256, 64]
    float* out = (float*)d_out;               // [256*64 centroids | N assignments]

    int n = in_sizes[0] / ND;
    int ntiles = (n + NTHREADS - 1) / NTHREADS;

    cudaMemcpyAsync(out, c, (size_t)NK * ND * sizeof(float),
                    cudaMemcpyDeviceToDevice, 0);

    cudaFuncSetAttribute(kmeans_hmma_kernel,
                         cudaFuncAttributeMaxDynamicSharedMemorySize, SMEM_TOTAL);
    kmeans_hmma_kernel<<<GRIDSZ, NTHREADS, SMEM_TOTAL>>>(x, c, out + NK * ND, n, ntiles);
}